// round 10
// baseline (speedup 1.0000x reference)
#include <cuda_runtime.h>
#include <cuda_bf16.h>

#define NCAM 16

// Per-camera smem layout (16 floats = 64B, four 16B groups):
//   grp0: r00 r10 r01 r11     (two column pairs)
//   grp1: r02 r12 t0  t1      (column pair + t pair)
//   grp2: f0  f1  c0  c1      (natural pairs)
//   grp3: r20 r21 r22 t2      (scalar row-3 for Z)
__device__ __align__(16) float g_params[NCAM * 16];

// ---------- f32x2 packed-math helpers (sm_103a) ----------
__device__ __forceinline__ unsigned long long pk2(float a, float b) {
    unsigned long long r;
    asm("mov.b64 %0, {%1, %2};" : "=l"(r) : "f"(a), "f"(b));
    return r;
}
__device__ __forceinline__ void upk2(unsigned long long v, float& a, float& b) {
    asm("mov.b64 {%0, %1}, %2;" : "=f"(a), "=f"(b) : "l"(v));
}
__device__ __forceinline__ unsigned long long fma2(unsigned long long a,
                                                   unsigned long long b,
                                                   unsigned long long c) {
    unsigned long long d;
    asm("fma.rn.f32x2 %0, %1, %2, %3;" : "=l"(d) : "l"(a), "l"(b), "l"(c));
    return d;
}
__device__ __forceinline__ unsigned long long mul2(unsigned long long a,
                                                   unsigned long long b) {
    unsigned long long d;
    asm("mul.rn.f32x2 %0, %1, %2;" : "=l"(d) : "l"(a), "l"(b));
    return d;
}
__device__ __forceinline__ float frcp(float x) {
    float r;
    asm("rcp.approx.f32 %0, %1;" : "=f"(r) : "f"(x));
    return r;
}
__device__ __forceinline__ void stcs_v2u64(void* p, unsigned long long a,
                                           unsigned long long b) {
    asm volatile("st.global.cs.v2.u64 [%0], {%1, %2};"
                 :: "l"(p), "l"(a), "l"(b) : "memory");
}

__global__ void prep_params_kernel(const float* __restrict__ R,
                                   const float* __restrict__ t,
                                   const float* __restrict__ f,
                                   const float* __restrict__ c)
{
    int s = threadIdx.x;
    if (s >= NCAM * 16) return;
    const int cam = s >> 4;
    const int k   = s & 15;
    const float* Rc = R + cam * 9;
    float v;
    switch (k) {
        case 0:  v = Rc[0]; break;  // r00
        case 1:  v = Rc[3]; break;  // r10
        case 2:  v = Rc[1]; break;  // r01
        case 3:  v = Rc[4]; break;  // r11
        case 4:  v = Rc[2]; break;  // r02
        case 5:  v = Rc[5]; break;  // r12
        case 6:  v = t[cam * 3 + 0]; break;
        case 7:  v = t[cam * 3 + 1]; break;
        case 8:  v = f[cam * 2 + 0]; break;
        case 9:  v = f[cam * 2 + 1]; break;
        case 10: v = c[cam * 2 + 0]; break;
        case 11: v = c[cam * 2 + 1]; break;
        case 12: v = Rc[6]; break;  // r20
        case 13: v = Rc[7]; break;  // r21
        case 14: v = Rc[8]; break;  // r22
        default: v = t[cam * 3 + 2]; break;  // t2
    }
    g_params[s] = v;
}

__global__ __launch_bounds__(256, 6)
void Projection_19713899889207_kernel(
    const float* __restrict__ pt3d,   // (3, Np) SoA
    float* __restrict__ out,          // (NC*Np, 2)
    int np)
{
    __shared__ __align__(16) float sp[NCAM * 16];
    const int tid = threadIdx.x;
    if (tid < NCAM * 16) sp[tid] = g_params[tid];
    __syncthreads();

    const int i = blockIdx.x * blockDim.x + tid;   // index of a PAIR of points
    const int np2 = np >> 1;
    if (i >= np2) return;

    // raw pair loads: u64 halves are (p0, p1)
    const unsigned long long x01 =
        __ldg(reinterpret_cast<const unsigned long long*>(pt3d) + i);
    const unsigned long long y01 =
        __ldg(reinterpret_cast<const unsigned long long*>(pt3d + (size_t)np) + i);
    const unsigned long long z01 =
        __ldg(reinterpret_cast<const unsigned long long*>(pt3d + 2 * (size_t)np) + i);

    // scalar coords (register-pair aliases, free) + camera-invariant dup packs
    float x0, x1, y0, y1, z0, z1;
    upk2(x01, x0, x1);
    upk2(y01, y0, y1);
    upk2(z01, z0, z1);
    const unsigned long long XX0 = pk2(x0, x0), XX1 = pk2(x1, x1);
    const unsigned long long YY0 = pk2(y0, y0), YY1 = pk2(y1, y1);
    const unsigned long long ZZ0 = pk2(z0, z0), ZZ1 = pk2(z1, z1);

    // output: one 16B store (2 points) per camera
    char* o = reinterpret_cast<char*>(out) + (size_t)i * 16;
    const size_t cam_stride = (size_t)np * 8;   // np points * 2 floats * 4B

    // FULL unroll: LDS at immediate smem offsets, no loop counter/branch.
    #pragma unroll
    for (int cam = 0; cam < NCAM; ++cam) {
        const ulonglong2* Q = reinterpret_cast<const ulonglong2*>(sp + cam * 16);
        const ulonglong2 qa = Q[0];   // ((r00,r10), (r01,r11))
        const ulonglong2 qb = Q[1];   // ((r02,r12), (t0,t1))
        const ulonglong2 qc = Q[2];   // ((f0,f1),   (c0,c1))
        const float4 r3 = reinterpret_cast<const float4*>(sp + cam * 16)[3];

        // depth (scalar): Z = r20*x + r21*y + r22*z + t2
        const float Za = fmaf(r3.x, x0, fmaf(r3.y, y0, fmaf(r3.z, z0, r3.w)));
        const float Zb = fmaf(r3.x, x1, fmaf(r3.y, y1, fmaf(r3.z, z1, r3.w)));
        const unsigned long long IZ0 = pk2(frcp(Za), frcp(Za));
        const unsigned long long IZ1 = pk2(frcp(Zb), frcp(Zb));

        // packed (X,Y) per point via column pairs
        const unsigned long long XY0 =
            fma2(qa.x, XX0, fma2(qa.y, YY0, fma2(qb.x, ZZ0, qb.y)));
        const unsigned long long XY1 =
            fma2(qa.x, XX1, fma2(qa.y, YY1, fma2(qb.x, ZZ1, qb.y)));

        // (u,v) = (X,Y)/Z * (f0,f1) + (c0,c1)  — already output layout
        const unsigned long long UV0 = fma2(mul2(XY0, IZ0), qc.x, qc.y);
        const unsigned long long UV1 = fma2(mul2(XY1, IZ1), qc.x, qc.y);

        stcs_v2u64(o + (size_t)cam * cam_stride, UV0, UV1);  // streaming STG.128
    }
}

extern "C" void kernel_launch(void* const* d_in, const int* in_sizes, int n_in,
                              void* d_out, int out_size)
{
    // metadata order: pt3d (3,Np) f32, R (16,3,3) f32, t (16,3) f32,
    //                 f (16,2) f32, c (16,2) f32, mask (16,Np) i32 (unused)
    const float* pt3d = (const float*)d_in[0];
    const float* R    = (const float*)d_in[1];
    const float* t    = (const float*)d_in[2];
    const float* f    = (const float*)d_in[3];
    const float* c    = (const float*)d_in[4];
    float* out        = (float*)d_out;

    const int np  = in_sizes[0] / 3;        // 2,000,000
    const int np2 = np / 2;

    prep_params_kernel<<<1, 256>>>(R, t, f, c);

    const int threads = 256;
    const int blocks  = (np2 + threads - 1) / threads;
    Projection_19713899889207_kernel<<<blocks, threads>>>(pt3d, out, np);
}